// round 6
// baseline (speedup 1.0000x reference)
#include <cuda_runtime.h>

#define NN 1024
#define BB 128
#define TS 32
#define NT 32
#define NTILES 528        // upper-triangular 32x32 tiles

// Partials [batch][tile]; final reduce streams contiguous rows.
__device__ float g_qpart[BB][NTILES];
__device__ unsigned int g_done = 0;

typedef unsigned long long u64;

static __device__ __forceinline__ u64 fma2(u64 a, u64 b, u64 c) {
    u64 d; asm("fma.rn.f32x2 %0, %1, %2, %3;" : "=l"(d) : "l"(a), "l"(b), "l"(c));
    return d;
}
static __device__ __forceinline__ u64 add2(u64 a, u64 b) {
    u64 d; asm("add.rn.f32x2 %0, %1, %2;" : "=l"(d) : "l"(a), "l"(b));
    return d;
}
static __device__ __forceinline__ u64 pack2(float lo, float hi) {
    u64 d; asm("mov.b64 %0, {%1, %2};" : "=l"(d) : "f"(lo), "f"(hi));
    return d;
}
static __device__ __forceinline__ void unpack2(u64 a, float& lo, float& hi) {
    asm("mov.b64 {%0, %1}, %2;" : "=f"(lo), "=f"(hi) : "l"(a));
}

__global__ __launch_bounds__(128, 4)
void potts_fused(const float* __restrict__ vec,
                 const float* __restrict__ W,
                 float* __restrict__ out)
{
    // W duplicated {w0,w0,w1,w1}: one LDS.128 feeds 2 FFMA2 (4 FMAs)
    __shared__ __align__(16) float4 Wd4[TS][TS / 2];      // 8 KB (16 float4 = 32 dup'd W per row)
    __shared__ float Wt[TS][TS + 1];                      // plain masked copy for rs/cs
    __shared__ u64 ViP[TS][64 + 1];                       // {v[b,i], v[b+64,i]}
    __shared__ u64 VjP[TS][64 + 1];
    __shared__ float rs[TS], cs[TS];                      // masked row / col sums
    __shared__ u64 comb[2][64];                           // per-half partial results
    __shared__ unsigned int s_rank;

    const int tid = threadIdx.x;

    // ---- compact triangular mapping: block -> (ti <= tj) ----
    const int u = (NTILES - 1) - (int)blockIdx.x;
    int r = (int)((sqrtf(8.0f * (float)u + 1.0f) - 1.0f) * 0.5f);
    while ((r + 1) * (r + 2) / 2 <= u) ++r;
    while (r * (r + 1) / 2 > u) --r;
    const int ti = NT - 1 - r;
    const int tj = NT - 1 - (u - r * (r + 1) / 2);
    const int i0 = ti * TS, j0 = tj * TS;
    const bool diag = (ti == tj);

    // ---- stage W tile (masked) into plain + duplicated layouts ----
    #pragma unroll
    for (int idx = tid; idx < TS * TS; idx += 128) {
        int rr = idx >> 5, c = idx & 31;
        float w = W[(i0 + rr) * NN + j0 + c];
        if (diag && c < rr) w = 0.0f;
        Wt[rr][c] = w;
        ((float2*)&Wd4[rr][0])[c] = make_float2(w, w);
    }
    // ---- stage v tiles as batch-pairs {b, b+64} ----
    #pragma unroll
    for (int idx = tid; idx < 64 * TS; idx += 128) {
        int b = idx >> 5, c = idx & 31;
        ViP[c][b] = pack2(vec[b * NN + i0 + c], vec[(b + 64) * NN + i0 + c]);
        VjP[c][b] = pack2(vec[b * NN + j0 + c], vec[(b + 64) * NN + j0 + c]);
    }
    __syncthreads();

    // ---- masked row/col sums (batch-independent) ----
    if (tid < TS) {
        float s = 0.0f;
        #pragma unroll
        for (int j = 0; j < TS; j++) s += Wt[tid][j];
        rs[tid] = s;
    } else if (tid < 2 * TS) {
        int j = tid - TS; float s = 0.0f;
        #pragma unroll
        for (int i = 0; i < TS; i++) s += Wt[i][j];
        cs[j] = s;
    }
    __syncthreads();

    // ---- per-batch-pair compute; warp-halves split the i-range ----
    const int half = tid >> 6;          // warps 0,1 -> i 0..15 ; warps 2,3 -> i 16..31
    const int b0 = tid & 63;
    const int ibase = half * 16;

    // lj = sum_j cs[j] * v[b,j]  (half 0 only; warp-uniform branch)
    u64 lj2 = 0ull;
    if (half == 0) {
        #pragma unroll
        for (int j = 0; j < TS; j++) {
            float c = cs[j];
            lj2 = fma2(pack2(c, c), VjP[j][b0], lj2);
        }
    }

    // linear i-terms over this half: Sh = sum rs[i]; na = sum rs[i]*v[b,i]
    u64 na2 = 0ull;
    float Sh = 0.0f;
    #pragma unroll
    for (int ii = 0; ii < 16; ii++) {
        const int i = ibase + ii;
        float rsv = rs[i];
        Sh += rsv;
        na2 = fma2(pack2(rsv, rsv), ViP[i][b0], na2);
    }

    // bilinear q = sum_{i,j} v_i W_ij v_j, j processed in 2 chunks of 16
    // so only 16 packed vj registers are live at a time.
    u64 q2 = 0ull;
    #pragma unroll
    for (int jc = 0; jc < 2; jc++) {
        u64 vj2[16];
        #pragma unroll
        for (int k = 0; k < 16; k++) vj2[k] = VjP[jc * 16 + k][b0];

        #pragma unroll 2
        for (int ii = 0; ii < 16; ii++) {
            const int i = ibase + ii;
            const ulonglong2* wr = ((const ulonglong2*)Wd4[i]) + jc * 8;
            u64 aacc = 0ull, bacc = 0ull;
            #pragma unroll
            for (int k = 0; k < 8; k++) {
                ulonglong2 w = wr[k];             // LDS.128 broadcast {w_{2k},w_{2k} | w_{2k+1},w_{2k+1}}
                aacc = fma2(w.x, vj2[2 * k + 0], aacc);
                bacc = fma2(w.y, vj2[2 * k + 1], bacc);
            }
            q2 = fma2(ViP[i][b0], add2(aacc, bacc), q2);
        }
    }

    // partial for this half: Sh - na - (half0: lj) + 2*q   (per packed lane)
    float qA, qB, nA, nB, lA, lB;
    unpack2(q2, qA, qB);
    unpack2(na2, nA, nB);
    unpack2(lj2, lA, lB);
    comb[half][b0] = pack2(Sh - nA - lA + 2.0f * qA,
                           Sh - nB - lB + 2.0f * qB);
    __syncthreads();

    if (tid < 64) {
        float a0, c0, a1, c1;
        unpack2(comb[0][tid], a0, c0);
        unpack2(comb[1][tid], a1, c1);
        g_qpart[tid][blockIdx.x]      = a0 + a1;
        g_qpart[tid + 64][blockIdx.x] = c0 + c1;
    }

    // ---- last-block fused reduction (deterministic; counter self-resets) ----
    __threadfence();
    __syncthreads();
    if (tid == 0) s_rank = atomicAdd(&g_done, 1u);
    __syncthreads();
    if (s_rank == NTILES - 1) {
        __threadfence();
        float s = 0.0f;
        const float4* p = (const float4*)(&g_qpart[tid][0]);
        #pragma unroll 4
        for (int k = 0; k < NTILES / 4; k++) {
            float4 v = p[k];
            s += v.x + v.y + v.z + v.w;
        }
        out[tid] = s;
        if (tid == 0) g_done = 0;
    }
}

extern "C" void kernel_launch(void* const* d_in, const int* in_sizes, int n_in,
                              void* d_out, int out_size)
{
    const float* vec = (const float*)d_in[0];   // vector        [128, 1024]
    const float* W   = (const float*)d_in[1];   // interactions  [1024, 1024]
    float* out = (float*)d_out;                 // [128]
    potts_fused<<<NTILES, 128>>>(vec, W, out);
}